// round 7
// baseline (speedup 1.0000x reference)
#include <cuda_runtime.h>
#include <cstdint>
#include <cstddef>

#define BB 32
#define NN 25200
#define NCC 20
#define KK 1024
#define MAXDET 300
#define CONF_T 0.001f
#define IOU_T 0.45f

// ---------- scratch (static device allocations; no cudaMalloc) ----------
__device__ float         g_conf[BB * NN];
__device__ unsigned char g_lab [BB * NN];
__device__ float4        g_tbox[BB * KK];
__device__ float         g_tsc [BB * KK];
__device__ int           g_tlb [BB * KK];
__device__ unsigned      g_msk [BB * KK * 32];   // TRANSPOSED mask: [b][w*1024+j], bit bi => i=32w+bi suppresses j (i<j)
// 13-bit score histogram (bits>>19), zero at load; k_topk re-zeroes after use so
// every graph replay sees a clean histogram (identical work every call).
__device__ unsigned      g_hist[BB * 2048];

// ---------- kernel A: scores + argmax labels + fused global histogram ----------
__global__ void k_score(const float* __restrict__ pred) {
    __shared__ float s[256 * 25];
    size_t base4 = (size_t)blockIdx.x * 1600;           // 6400 floats = 1600 float4
    const float4* p4 = (const float4*)pred + base4;
    float4* s4 = (float4*)s;
    for (int k = threadIdx.x; k < 1600; k += 256) s4[k] = p4[k];
    __syncthreads();
    const float* row = s + threadIdx.x * 25;
    float obj  = row[4];
    float best = row[5];
    int   bl   = 0;
#pragma unroll
    for (int c = 1; c < NCC; c++) {
        float v = row[5 + c];
        if (v > best) { best = v; bl = c; }  // first-max like jnp.argmax
    }
    float conf = __fmul_rn(obj, best);
    int r = blockIdx.x * 256 + threadIdx.x;
    g_conf[r] = conf;
    g_lab[r]  = (unsigned char)bl;
    if (conf > CONF_T) {
        int b = r / NN;
        atomicAdd(&g_hist[b * 2048 + (__float_as_uint(conf) >> 19)], 1u);  // REDG, hidden under DRAM stream
    }
}

// ---------- kernel B1: exact stable top-1024 via bucket COUNTING SORT (2 block barriers in sort path) ----------
__global__ void k_topk(const float* __restrict__ pred) {
    extern __shared__ unsigned sh[];
    unsigned long long* skey = (unsigned long long*)sh;  // 8192 keys (64 KB) = sh[0..16383]
    unsigned* h    = sh + 16384;          // 2048 bucket counts
    int*      sb   = (int*)(sh + 18432);  // 2048 descending base ranks
    int*      bcnt = (int*)(sh + 20480);  // 2048 arrival counters
    int*      ctrl = (int*)(sh + 22528);  // 16: [0]=Tmax [3]=fallback flag
    unsigned* wsc  = sh + 22544;          // 64: warp totals + tails

    int b = blockIdx.x;
    int tid = threadIdx.x;
    int lane = tid & 31, wid = tid >> 5;
    const float* sc = g_conf + (size_t)b * NN;

    // consume global histogram, then re-zero it for the next graph replay
    {
        unsigned* gh = g_hist + b * 2048;
        h[tid]        = gh[tid];
        h[tid + 1024] = gh[tid + 1024];
        gh[tid] = 0; gh[tid + 1024] = 0;
    }
    bcnt[tid] = 0; bcnt[tid + 1024] = 0;
#pragma unroll
    for (int q = 0; q < 8; q++) skey[tid + q * 1024] = 0ull;
    if (tid < 16) ctrl[tid] = (tid == 0) ? -1 : 0;
    __syncthreads();

    // suffix-scan over 1024 bucket-pairs via warp shuffles -> S[t] = sum_{t'>=t} pair[t']
    unsigned ps = h[2 * tid] + h[2 * tid + 1];
    unsigned s = ps;
#pragma unroll
    for (int off = 1; off < 32; off <<= 1) {
        unsigned v = __shfl_down_sync(0xffffffffu, s, off);
        if (lane + off < 32) s += v;
    }
    if (lane == 0) wsc[wid] = s;
    __syncthreads();
    if (wid == 0) {
        unsigned t = wsc[lane];
#pragma unroll
        for (int off = 1; off < 32; off <<= 1) {
            unsigned v = __shfl_down_sync(0xffffffffu, t, off);
            if (lane + off < 32) t += v;
        }
        unsigned tail = __shfl_down_sync(0xffffffffu, t, 1);
        if (lane == 31) tail = 0;
        wsc[32 + lane] = tail;
    }
    __syncthreads();
    unsigned S = s + wsc[32 + wid];       // suffix including pair tid
    unsigned Snext = S - ps;              // suffix of pairs > tid  (S[1024]=0 handled naturally)
    // descending base rank per bucket: sb[k] = #cands in buckets > k
    sb[2 * tid + 1] = (int)Snext;
    sb[2 * tid]     = (int)(Snext + h[2 * tid + 1]);
    // T = max bucket whose suffix count >= KK (suffix(2t)=S, suffix(2t+1)=Snext+h[2t+1])
    if (Snext + h[2 * tid + 1] >= KK) atomicMax(&ctrl[0], 2 * tid + 1);
    else if (S >= KK)                 atomicMax(&ctrl[0], 2 * tid);
    __syncthreads();
    int T = ctrl[0] < 0 ? 0 : ctrl[0];

    // counting-sort scatter: rank = bucket base + arrival offset (within-bucket unordered)
    for (int n = tid; n < NN; n += 1024) {
        float v = sc[n];
        if (v > CONF_T) {
            int bk = (int)(__float_as_uint(v) >> 19);
            if (bk >= T) {
                int p = sb[bk] + atomicAdd(&bcnt[bk], 1);
                if (p < 8192)
                    skey[p] = ((unsigned long long)__float_as_uint(v) << 32)
                            | (unsigned long long)(0xFFFFFFFFu - (unsigned)n);
            }
        }
    }
    // fallback guard: any top-relevant bucket too large for warp odd-even sort?
    {
        if (sb[tid] < KK && bcnt[tid] > 256) atomicOr(&ctrl[3], 1);
        if (sb[tid + 1024] < KK && bcnt[tid + 1024] > 256) atomicOr(&ctrl[3], 1);
    }
    __syncthreads();

    if (ctrl[3] == 0) {
        // per-bucket stable sort: one warp per bucket, odd-even transposition, NO block barriers.
        // only buckets that can reach rank < 1024 matter.
        for (int bk = wid; bk < 2048; bk += 32) {
            int base = sb[bk];
            if (base >= KK) continue;
            int m = bcnt[bk];
            if (m > 8192 - base) m = 8192 - base;
            if (m <= 1) continue;
            for (int ph = 0; ph < m; ph++) {
                for (int i = (ph & 1) + 2 * lane; i + 1 < m; i += 64) {
                    unsigned long long a = skey[base + i], c = skey[base + i + 1];
                    if (a < c) { skey[base + i] = c; skey[base + i + 1] = a; }
                }
                __syncwarp();
            }
        }
    } else {
        // pathological bucket (>256 identical 13-bit prefixes): generic full bitonic, descending
        for (int k = 2; k <= 8192; k <<= 1) {
            for (int j = k >> 1; j > 0; j >>= 1) {
                for (int t2 = tid; t2 < 8192; t2 += 1024) {
                    int ixj = t2 ^ j;
                    if (ixj > t2) {
                        unsigned long long a = skey[t2], c = skey[ixj];
                        if (((t2 & k) == 0) ? (a < c) : (a > c)) { skey[t2] = c; skey[ixj] = a; }
                    }
                }
                __syncthreads();
            }
        }
    }
    __syncthreads();

    // emit top-1024: score, label, xywh->xyxy (non-fused to match ref)
    {
        unsigned long long key = skey[tid];
        unsigned sbits = (unsigned)(key >> 32);
        float score; int n;
        if (sbits) { score = __uint_as_float(sbits); n = (int)(0xFFFFFFFFu - (unsigned)key); }
        else       { score = -1.0f; n = 0; }
        const float* pr = pred + ((size_t)b * NN + n) * 25;
        float x = pr[0], y = pr[1], w = pr[2], h2 = pr[3];
        float hw = __fmul_rn(w, 0.5f), hh = __fmul_rn(h2, 0.5f);
        int idx = b * KK + tid;
        g_tbox[idx] = make_float4(__fsub_rn(x, hw), __fsub_rn(y, hh),
                                  __fadd_rn(x, hw), __fadd_rn(y, hh));
        g_tsc[idx]  = score;
        g_tlb[idx]  = (int)g_lab[(size_t)b * NN + n];
    }
}

// ---------- kernel B2: pairwise IoU -> TRANSPOSED mask, load-balanced strip pairing ----------
// Block (wp, b) handles word-strips w=wp and w=31-wp: combined j-count is constant (1056).
// g_msk[b][w*1024+j] bit bi set <=> i=32w+bi < j AND iou(i,j) > thr. top==0 words never written
// (k_nms masks the self word), all other needed words written exactly once.
__global__ void k_iou() {
    __shared__ float ix1[64], iy1[64], ix2[64], iy2[64], iar[64];
    int b = blockIdx.y, wp = blockIdx.x, tid = threadIdx.x;

    if (tid < 64) {
        int strip = (tid < 32) ? wp : (31 - wp);
        int i = strip * 32 + (tid & 31);
        float4 bx = g_tbox[b * KK + i];
        float off = __fmul_rn((float)g_tlb[b * KK + i], 4096.0f);
        // offsets applied BEFORE area: fp32 quantization at +label*4096 must match ref
        float ox1 = __fadd_rn(bx.x, off), oy1 = __fadd_rn(bx.y, off);
        float ox2 = __fadd_rn(bx.z, off), oy2 = __fadd_rn(bx.w, off);
        ix1[tid] = ox1; iy1[tid] = oy1; ix2[tid] = ox2; iy2[tid] = oy2;
        iar[tid] = __fmul_rn(__fsub_rn(ox2, ox1), __fsub_rn(oy2, oy1));
    }
    __syncthreads();

#pragma unroll
    for (int half = 0; half < 2; half++) {
        int w = half ? (31 - wp) : wp;
        int sbase = half * 32;
        for (int j = 32 * w + tid; j < 1024; j += 256) {
            float4 bx = g_tbox[b * KK + j];
            float off = __fmul_rn((float)g_tlb[b * KK + j], 4096.0f);
            float jx1 = __fadd_rn(bx.x, off), jy1 = __fadd_rn(bx.y, off);
            float jx2 = __fadd_rn(bx.z, off), jy2 = __fadd_rn(bx.w, off);
            float aj  = __fmul_rn(__fsub_rn(jx2, jx1), __fsub_rn(jy2, jy1));
            int top = j - 32 * w; if (top > 32) top = 32;
            unsigned bits = 0;
            for (int bi = 0; bi < top; bi++) {   // smem broadcast reads
                float ltx = fmaxf(jx1, ix1[sbase + bi]), lty = fmaxf(jy1, iy1[sbase + bi]);
                float rbx = fminf(jx2, ix2[sbase + bi]), rby = fminf(jy2, iy2[sbase + bi]);
                float ww = fmaxf(__fsub_rn(rbx, ltx), 0.0f);
                float hh = fmaxf(__fsub_rn(rby, lty), 0.0f);
                float inter = __fmul_rn(ww, hh);
                float den = __fadd_rn(__fsub_rn(__fadd_rn(iar[sbase + bi], aj), inter), 1e-9f);
                // margin compare: exact decision without div except in a ~1e-4 band
                float d = __fsub_rn(inter, __fmul_rn(IOU_T, den));
                float marg = __fmul_rn(den, 1e-4f);
                bool sup;
                if (fabsf(d) <= marg) sup = (inter / den) > IOU_T;   // rare exact IEEE path
                else                  sup = d > 0.0f;
                if (sup) bits |= (1u << bi);
            }
            if (top > 0) g_msk[(size_t)b * 32768 + w * 1024 + j] = bits;  // coalesced over j
        }
    }
}

// ---------- kernel B3: Jacobi-fixpoint greedy NMS + clip/filter + top-300 compaction ----------
__global__ void k_nms(const int* __restrict__ imw, const int* __restrict__ imh,
                      float* __restrict__ out) {
    extern __shared__ unsigned sh[];
    unsigned* cm    = sh;                    // 32768 words, [w][j] (lower triangle valid)
    unsigned* kwsA  = sh + 32768;            // 32
    unsigned* kwsB  = sh + 32800;            // 32
    unsigned* wcnt  = sh + 32832;            // 32
    unsigned* wbal  = sh + 32864;            // 32
    int*      ctrl  = (int*)(sh + 32896);    // 4
    float4*   cbox  = (float4*)(sh + 32900); // 300 (32900*4 % 16 == 0)
    float*    cscore = (float*)(cbox + MAXDET);
    int*      clabel = (int*)(cscore + MAXDET);

    int b = blockIdx.x, tid = threadIdx.x;
    int lane = tid & 31, wid = tid >> 5;

    // vectorized lower-triangle mask load (4-aligned j groups share the same w, j>>5)
    for (int base = tid * 4; base < 32768; base += 4096) {
        int w = base >> 10, j0 = base & 1023;
        if (w <= (j0 >> 5))
            *(uint4*)(cm + base) = *(const uint4*)(g_msk + (size_t)b * 32768 + base);
    }
    float score = g_tsc[b * KK + tid];
    bool cnd = score > CONF_T;
    unsigned cbal = __ballot_sync(0xffffffffu, cnd);
    if (lane == 0) kwsA[wid] = cbal;
    __syncthreads();

    // Jacobi fixpoint: keep[j] = cand[j] & !exists(i<j: sup(i,j) & keep[i])
    // converges to the unique greedy solution; self word masked to lane-lower bits
    unsigned* cur = kwsA;
    unsigned* nxt = kwsB;
    unsigned mself = cm[wid * 1024 + tid] & ((1u << lane) - 1u);
    for (int it = 0; it < 1025; it++) {
        unsigned sup = mself & cur[wid];
        for (int w = 0; w < wid; w++)
            sup |= cm[w * 1024 + tid] & cur[w];  // lanes->consecutive j: conflict-free; cur[w] broadcast
        bool nk = cnd && (sup == 0u);
        unsigned nb = __ballot_sync(0xffffffffu, nk);
        if (lane == 0) nxt[wid] = nb;
        int changed = __syncthreads_or((int)(nb != cur[wid]));
        if (!changed) break;
        unsigned* t = cur; cur = nxt; nxt = t;
    }

    bool keep = (cur[wid] >> lane) & 1u;
    float fw = (float)(*imw), fh = (float)(*imh);
    float4 bx = g_tbox[b * KK + tid];
    float x1c = fminf(fmaxf(bx.x, 0.0f), fw);
    float y1c = fminf(fmaxf(bx.y, 0.0f), fh);
    float x2c = fminf(fmaxf(bx.z, 0.0f), fw);
    float y2c = fminf(fmaxf(bx.w, 0.0f), fh);
    float bw  = __fsub_rn(x2c, x1c);
    float bh2 = __fsub_rn(y2c, y1c);
    bool valid = keep && (bw > 0.0f) && (bh2 > 0.0f) && (bw >= 1.0f) && (bh2 >= 1.0f);

    unsigned vb = __ballot_sync(0xffffffffu, valid);
    if (lane == 0) { wcnt[wid] = __popc(vb); wbal[wid] = vb; }
    __syncthreads();
    if (tid == 0) {
        int acc2 = 0;
        for (int q = 0; q < 32; q++) { int c = wcnt[q]; wcnt[q] = acc2; acc2 += c; }
        ctrl[0] = acc2;
    }
    __syncthreads();
    if (valid) {
        int rank = wcnt[wid] + __popc(wbal[wid] & ((1u << lane) - 1u));
        if (rank < MAXDET) {
            cbox[rank]   = make_float4(x1c, y1c, x2c, y2c);
            cscore[rank] = score;
            clabel[rank] = g_tlb[b * KK + tid];
        }
    }
    __syncthreads();

    int total = ctrl[0]; if (total > MAXDET) total = MAXDET;
    if (tid < MAXDET) {
        float4 ob; float os, ol, ov;
        if (tid < total) { ob = cbox[tid]; os = cscore[tid]; ol = (float)clabel[tid]; ov = 1.0f; }
        else             { ob = make_float4(0, 0, 0, 0); os = 0.0f; ol = 0.0f; ov = 0.0f; }
        float* obox = out + ((size_t)b * MAXDET + tid) * 4;
        obox[0] = ob.x; obox[1] = ob.y; obox[2] = ob.z; obox[3] = ob.w;
        out[BB * MAXDET * 4 + b * MAXDET + tid] = os;   // det_scores
        out[BB * MAXDET * 5 + b * MAXDET + tid] = ol;   // det_labels (as f32)
        out[BB * MAXDET * 6 + b * MAXDET + tid] = ov;   // vm (as f32)
    }
}

extern "C" void kernel_launch(void* const* d_in, const int* in_sizes, int n_in,
                              void* d_out, int out_size) {
    const float* pred = (const float*)d_in[0];
    const int*   imh  = (const int*)d_in[1];
    const int*   imw  = (const int*)d_in[2];
    float* out = (float*)d_out;

    cudaFuncSetAttribute((const void*)k_topk,
                         cudaFuncAttributeMaxDynamicSharedMemorySize, 90432);
    cudaFuncSetAttribute((const void*)k_nms,
                         cudaFuncAttributeMaxDynamicSharedMemorySize, 138800);

    k_score<<<(BB * NN) / 256, 256>>>(pred);
    k_topk<<<BB, 1024, 90432>>>(pred);
    k_iou<<<dim3(16, BB), 256>>>();
    k_nms<<<BB, 1024, 138800>>>(imw, imh, out);
}

// round 9
// speedup vs baseline: 1.2728x; 1.2728x over previous
#include <cuda_runtime.h>
#include <cstdint>
#include <cstddef>

#define BB 32
#define NN 25200
#define NCC 20
#define KK 1024
#define MAXDET 300
#define CONF_T 0.001f
#define IOU_T 0.45f

// ---------- scratch (static device allocations; no cudaMalloc) ----------
__device__ float4        g_tbox[BB * KK];
__device__ float         g_tsc [BB * KK];
__device__ int           g_tlb [BB * KK];
__device__ unsigned      g_msk [BB * KK * 32];   // TRANSPOSED mask: [b][w*1024+j], bit bi => i=32w+bi suppresses j (i<j)

// ---------- kernel B1: FUSED score + exact stable top-1024 per batch ----------
// One block per batch streams its 2.52 MB of pred through smem staging (coalesced
// float4), scores rows (conf kept in registers/local), builds a 13-bit histogram,
// thresholds, collects, hybrid-bitonic sorts, emits. __launch_bounds__ keeps the
// kernel launchable at 1024 threads (spilled creg words go through L1 once).
__global__ void __launch_bounds__(1024, 1) k_topk(const float* __restrict__ pred) {
    extern __shared__ unsigned sh[];
    // region R: sh[0..25599] = 100 KB staging; cand overlays sh[0..16383] after pass A
    float*              stage = (float*)sh;
    unsigned long long* cand  = (unsigned long long*)sh;   // 8192 keys (64 KB)
    unsigned* h    = sh + 25600;                 // 2048 bucket counts (bits>>19)
    int*      ctrl = (int*)(sh + 27648);         // 16: [0]=T(bucket) [2]=cnt
    unsigned* wsc  = sh + 27664;                 // 64: warp totals + tails
    unsigned char* slab = (unsigned char*)(sh + 27728);    // 25200 labels

    int b = blockIdx.x;
    int tid = threadIdx.x;
    int lane = tid & 31, wid = tid >> 5;

    h[tid] = 0; h[tid + 1024] = 0;
    if (tid < 16) ctrl[tid] = (tid == 0) ? -1 : 0;
    __syncthreads();

    // ---- pass A: stream pred in 25 chunks of 1024 rows; score; histogram ----
    float creg[25];
    const float* pb = pred + (size_t)b * NN * 25;
#pragma unroll
    for (int c = 0; c < 25; c++) {
        int rows = (c < 24) ? 1024 : (NN - 24 * 1024);           // 1024 / 624
        int n4 = rows * 25 / 4;                                  // rows*25 % 4 == 0
        const float4* p4 = (const float4*)(pb + (size_t)c * 25600); // 25600 % 4 == 0 -> aligned
        float4* s4 = (float4*)stage;
        for (int k = tid; k < n4; k += 1024) s4[k] = p4[k];
        __syncthreads();
        float conf = -1.0f;
        if (tid < rows) {
            const float* row = stage + tid * 25;                 // stride 25: conflict-free
            float obj  = row[4];
            float best = row[5];
            int   bl   = 0;
#pragma unroll
            for (int q = 1; q < NCC; q++) {
                float v = row[5 + q];
                if (v > best) { best = v; bl = q; }              // first-max like jnp.argmax
            }
            conf = __fmul_rn(obj, best);
            slab[c * 1024 + tid] = (unsigned char)bl;
            if (conf > CONF_T)
                atomicAdd(&h[__float_as_uint(conf) >> 19], 1u);
        }
        creg[c] = conf;
        __syncthreads();
    }

    // ---- threshold: suffix-scan over 1024 bucket-pairs via warp shuffles ----
    unsigned ps = h[2 * tid] + h[2 * tid + 1];
    unsigned s = ps;
#pragma unroll
    for (int off = 1; off < 32; off <<= 1) {
        unsigned v = __shfl_down_sync(0xffffffffu, s, off);
        if (lane + off < 32) s += v;
    }
    if (lane == 0) wsc[wid] = s;
    __syncthreads();
    if (wid == 0) {
        unsigned t = wsc[lane];
#pragma unroll
        for (int off = 1; off < 32; off <<= 1) {
            unsigned v = __shfl_down_sync(0xffffffffu, t, off);
            if (lane + off < 32) t += v;
        }
        unsigned tail = __shfl_down_sync(0xffffffffu, t, 1);
        if (lane == 31) tail = 0;
        wsc[32 + lane] = tail;
    }
    __syncthreads();
    unsigned S = s + wsc[32 + wid];       // suffix including pair tid
    unsigned Snext = S - ps;              // suffix of pairs > tid
    // T = max bucket whose suffix count >= KK
    if (Snext + h[2 * tid + 1] >= KK) atomicMax(&ctrl[0], 2 * tid + 1);
    else if (S >= KK)                 atomicMax(&ctrl[0], 2 * tid);
    __syncthreads();
    unsigned T = (unsigned)(ctrl[0] < 0 ? 0 : ctrl[0]);

    // ---- collect candidates (creg -> cand, overlaying dead stage) ----
#pragma unroll
    for (int c = 0; c < 25; c++) {
        float v = creg[c];
        if (v > CONF_T) {
            unsigned bits = __float_as_uint(v);
            if ((bits >> 19) >= T) {
                int p = atomicAdd(&ctrl[2], 1);
                if (p < 8192) {
                    unsigned n = (unsigned)(c * 1024 + tid);
                    cand[p] = ((unsigned long long)bits << 32)
                            | (unsigned long long)(0xFFFFFFFFu - n);
                }
            }
        }
    }
    __syncthreads();
    int cnt = ctrl[2]; if (cnt > 8192) cnt = 8192;

    if (cnt <= 2048) {
        // ---- hybrid bitonic sort of 2048 keys, descending ----
        for (int p = cnt + tid; p < 2048; p += 1024) cand[p] = 0ull;
        __syncthreads();
        unsigned long long va = cand[tid], vb = cand[tid + 1024];
#pragma unroll
        for (int k = 2; k <= 32; k <<= 1) {
#pragma unroll
            for (int j = k >> 1; j >= 1; j >>= 1) {
                bool lower = (tid & j) == 0;
                {
                    unsigned long long pa = __shfl_xor_sync(0xffffffffu, va, j);
                    bool dir = (tid & k) == 0;
                    va = (((dir == lower) ? (va > pa) : (va < pa))) ? va : pa;
                }
                {
                    unsigned long long pb2 = __shfl_xor_sync(0xffffffffu, vb, j);
                    bool dir = ((tid + 1024) & k) == 0;
                    vb = (((dir == lower) ? (vb > pb2) : (vb < pb2))) ? vb : pb2;
                }
            }
        }
        cand[tid] = va; cand[tid + 1024] = vb;
        __syncthreads();
        for (int k = 64; k <= 2048; k <<= 1) {
            for (int j = k >> 1; j >= 32; j >>= 1) {
                for (int t2 = tid; t2 < 2048; t2 += 1024) {
                    int ixj = t2 ^ j;
                    if (ixj > t2) {
                        unsigned long long a = cand[t2], c2 = cand[ixj];
                        if (((t2 & k) == 0) ? (a < c2) : (a > c2)) { cand[t2] = c2; cand[ixj] = a; }
                    }
                }
                __syncthreads();
            }
            va = cand[tid]; vb = cand[tid + 1024];
#pragma unroll
            for (int j = 16; j >= 1; j >>= 1) {
                bool lower = (tid & j) == 0;
                {
                    unsigned long long pa = __shfl_xor_sync(0xffffffffu, va, j);
                    bool dir = (tid & k) == 0;
                    va = (((dir == lower) ? (va > pa) : (va < pa))) ? va : pa;
                }
                {
                    unsigned long long pb2 = __shfl_xor_sync(0xffffffffu, vb, j);
                    bool dir = ((tid + 1024) & k) == 0;
                    vb = (((dir == lower) ? (vb > pb2) : (vb < pb2))) ? vb : pb2;
                }
            }
            cand[tid] = va; cand[tid + 1024] = vb;
            __syncthreads();
        }
    } else {
        // ---- generic fallback (rare): plain smem bitonic up to 8192 ----
        int n2 = 2048; while (n2 < cnt) n2 <<= 1;
        for (int p = cnt + tid; p < n2; p += 1024) cand[p] = 0ull;
        __syncthreads();
        for (int k = 2; k <= n2; k <<= 1) {
            for (int j = k >> 1; j > 0; j >>= 1) {
                for (int t2 = tid; t2 < n2; t2 += 1024) {
                    int ixj = t2 ^ j;
                    if (ixj > t2) {
                        unsigned long long a = cand[t2], c2 = cand[ixj];
                        if (((t2 & k) == 0) ? (a < c2) : (a > c2)) { cand[t2] = c2; cand[ixj] = a; }
                    }
                }
                __syncthreads();
            }
        }
    }

    // ---- emit top-1024: score, label, xywh->xyxy (non-fused to match ref) ----
    {
        unsigned long long key = cand[tid];
        unsigned sbits = (unsigned)(key >> 32);
        float score; int n;
        if (sbits) { score = __uint_as_float(sbits); n = (int)(0xFFFFFFFFu - (unsigned)key); }
        else       { score = -1.0f; n = 0; }
        const float* pr = pb + (size_t)n * 25;
        float x = pr[0], y = pr[1], w = pr[2], h2 = pr[3];
        float hw = __fmul_rn(w, 0.5f), hh = __fmul_rn(h2, 0.5f);
        int idx = b * KK + tid;
        g_tbox[idx] = make_float4(__fsub_rn(x, hw), __fsub_rn(y, hh),
                                  __fadd_rn(x, hw), __fadd_rn(y, hh));
        g_tsc[idx]  = score;
        g_tlb[idx]  = (int)slab[n];
    }
}

// ---------- kernel B2: pairwise IoU -> TRANSPOSED mask, load-balanced strip pairing ----------
// Block (wp, b) handles word-strips w=wp and w=31-wp: combined j-count is constant (1056).
// g_msk[b][w*1024+j] bit bi set <=> i=32w+bi < j AND iou(i,j) > thr. top==0 words never written
// (k_nms masks the self word), all other needed words written exactly once.
__global__ void k_iou() {
    __shared__ float ix1[64], iy1[64], ix2[64], iy2[64], iar[64];
    int b = blockIdx.y, wp = blockIdx.x, tid = threadIdx.x;

    if (tid < 64) {
        int strip = (tid < 32) ? wp : (31 - wp);
        int i = strip * 32 + (tid & 31);
        float4 bx = g_tbox[b * KK + i];
        float off = __fmul_rn((float)g_tlb[b * KK + i], 4096.0f);
        // offsets applied BEFORE area: fp32 quantization at +label*4096 must match ref
        float ox1 = __fadd_rn(bx.x, off), oy1 = __fadd_rn(bx.y, off);
        float ox2 = __fadd_rn(bx.z, off), oy2 = __fadd_rn(bx.w, off);
        ix1[tid] = ox1; iy1[tid] = oy1; ix2[tid] = ox2; iy2[tid] = oy2;
        iar[tid] = __fmul_rn(__fsub_rn(ox2, ox1), __fsub_rn(oy2, oy1));
    }
    __syncthreads();

#pragma unroll
    for (int half = 0; half < 2; half++) {
        int w = half ? (31 - wp) : wp;
        int sbase = half * 32;
        for (int j = 32 * w + tid; j < 1024; j += 256) {
            float4 bx = g_tbox[b * KK + j];
            float off = __fmul_rn((float)g_tlb[b * KK + j], 4096.0f);
            float jx1 = __fadd_rn(bx.x, off), jy1 = __fadd_rn(bx.y, off);
            float jx2 = __fadd_rn(bx.z, off), jy2 = __fadd_rn(bx.w, off);
            float aj  = __fmul_rn(__fsub_rn(jx2, jx1), __fsub_rn(jy2, jy1));
            int top = j - 32 * w; if (top > 32) top = 32;
            unsigned bits = 0;
            for (int bi = 0; bi < top; bi++) {   // smem broadcast reads
                float ltx = fmaxf(jx1, ix1[sbase + bi]), lty = fmaxf(jy1, iy1[sbase + bi]);
                float rbx = fminf(jx2, ix2[sbase + bi]), rby = fminf(jy2, iy2[sbase + bi]);
                float ww = fmaxf(__fsub_rn(rbx, ltx), 0.0f);
                float hh = fmaxf(__fsub_rn(rby, lty), 0.0f);
                float inter = __fmul_rn(ww, hh);
                float den = __fadd_rn(__fsub_rn(__fadd_rn(iar[sbase + bi], aj), inter), 1e-9f);
                // margin compare: exact decision without div except in a ~1e-4 band
                float d = __fsub_rn(inter, __fmul_rn(IOU_T, den));
                float marg = __fmul_rn(den, 1e-4f);
                bool sup;
                if (fabsf(d) <= marg) sup = (inter / den) > IOU_T;   // rare exact IEEE path
                else                  sup = d > 0.0f;
                if (sup) bits |= (1u << bi);
            }
            if (top > 0) g_msk[(size_t)b * 32768 + w * 1024 + j] = bits;  // coalesced over j
        }
    }
}

// ---------- kernel B3: Jacobi-fixpoint greedy NMS + clip/filter + top-300 compaction ----------
__global__ void __launch_bounds__(1024, 1) k_nms(const int* __restrict__ imw, const int* __restrict__ imh,
                      float* __restrict__ out) {
    extern __shared__ unsigned sh[];
    unsigned* cm    = sh;                    // 32768 words, [w][j] (lower triangle valid)
    unsigned* kwsA  = sh + 32768;            // 32
    unsigned* kwsB  = sh + 32800;            // 32
    unsigned* wcnt  = sh + 32832;            // 32
    unsigned* wbal  = sh + 32864;            // 32
    int*      ctrl  = (int*)(sh + 32896);    // 4
    float4*   cbox  = (float4*)(sh + 32900); // 300 (32900*4 % 16 == 0)
    float*    cscore = (float*)(cbox + MAXDET);
    int*      clabel = (int*)(cscore + MAXDET);

    int b = blockIdx.x, tid = threadIdx.x;
    int lane = tid & 31, wid = tid >> 5;

    // vectorized lower-triangle mask load (4-aligned j groups share the same w, j>>5)
    for (int base = tid * 4; base < 32768; base += 4096) {
        int w = base >> 10, j0 = base & 1023;
        if (w <= (j0 >> 5))
            *(uint4*)(cm + base) = *(const uint4*)(g_msk + (size_t)b * 32768 + base);
    }
    float score = g_tsc[b * KK + tid];
    bool cnd = score > CONF_T;
    unsigned cbal = __ballot_sync(0xffffffffu, cnd);
    if (lane == 0) kwsA[wid] = cbal;
    __syncthreads();

    // Jacobi fixpoint: keep[j] = cand[j] & !exists(i<j: sup(i,j) & keep[i])
    // converges to the unique greedy solution; self word masked to lane-lower bits
    unsigned* cur = kwsA;
    unsigned* nxt = kwsB;
    unsigned mself = cm[wid * 1024 + tid] & ((1u << lane) - 1u);
    for (int it = 0; it < 1025; it++) {
        unsigned sup = mself & cur[wid];
        for (int w = 0; w < wid; w++)
            sup |= cm[w * 1024 + tid] & cur[w];  // lanes->consecutive j: conflict-free; cur[w] broadcast
        bool nk = cnd && (sup == 0u);
        unsigned nb = __ballot_sync(0xffffffffu, nk);
        if (lane == 0) nxt[wid] = nb;
        int changed = __syncthreads_or((int)(nb != cur[wid]));
        if (!changed) break;
        unsigned* t = cur; cur = nxt; nxt = t;
    }

    bool keep = (cur[wid] >> lane) & 1u;
    float fw = (float)(*imw), fh = (float)(*imh);
    float4 bx = g_tbox[b * KK + tid];
    float x1c = fminf(fmaxf(bx.x, 0.0f), fw);
    float y1c = fminf(fmaxf(bx.y, 0.0f), fh);
    float x2c = fminf(fmaxf(bx.z, 0.0f), fw);
    float y2c = fminf(fmaxf(bx.w, 0.0f), fh);
    float bw  = __fsub_rn(x2c, x1c);
    float bh2 = __fsub_rn(y2c, y1c);
    bool valid = keep && (bw > 0.0f) && (bh2 > 0.0f) && (bw >= 1.0f) && (bh2 >= 1.0f);

    unsigned vb = __ballot_sync(0xffffffffu, valid);
    if (lane == 0) { wcnt[wid] = __popc(vb); wbal[wid] = vb; }
    __syncthreads();
    if (tid == 0) {
        int acc2 = 0;
        for (int q = 0; q < 32; q++) { int c = wcnt[q]; wcnt[q] = acc2; acc2 += c; }
        ctrl[0] = acc2;
    }
    __syncthreads();
    if (valid) {
        int rank = wcnt[wid] + __popc(wbal[wid] & ((1u << lane) - 1u));
        if (rank < MAXDET) {
            cbox[rank]   = make_float4(x1c, y1c, x2c, y2c);
            cscore[rank] = score;
            clabel[rank] = g_tlb[b * KK + tid];
        }
    }
    __syncthreads();

    int total = ctrl[0]; if (total > MAXDET) total = MAXDET;
    if (tid < MAXDET) {
        float4 ob; float os, ol, ov;
        if (tid < total) { ob = cbox[tid]; os = cscore[tid]; ol = (float)clabel[tid]; ov = 1.0f; }
        else             { ob = make_float4(0, 0, 0, 0); os = 0.0f; ol = 0.0f; ov = 0.0f; }
        float* obox = out + ((size_t)b * MAXDET + tid) * 4;
        obox[0] = ob.x; obox[1] = ob.y; obox[2] = ob.z; obox[3] = ob.w;
        out[BB * MAXDET * 4 + b * MAXDET + tid] = os;   // det_scores
        out[BB * MAXDET * 5 + b * MAXDET + tid] = ol;   // det_labels (as f32)
        out[BB * MAXDET * 6 + b * MAXDET + tid] = ov;   // vm (as f32)
    }
}

extern "C" void kernel_launch(void* const* d_in, const int* in_sizes, int n_in,
                              void* d_out, int out_size) {
    const float* pred = (const float*)d_in[0];
    const int*   imh  = (const int*)d_in[1];
    const int*   imw  = (const int*)d_in[2];
    float* out = (float*)d_out;

    // smem: 27728 words + 25200 bytes (labels) = 136112 B -> round up
    cudaFuncSetAttribute((const void*)k_topk,
                         cudaFuncAttributeMaxDynamicSharedMemorySize, 136192);
    cudaFuncSetAttribute((const void*)k_nms,
                         cudaFuncAttributeMaxDynamicSharedMemorySize, 138800);

    k_topk<<<BB, 1024, 136192>>>(pred);
    k_iou<<<dim3(16, BB), 256>>>();
    k_nms<<<BB, 1024, 138800>>>(imw, imh, out);
}

// round 10
// speedup vs baseline: 1.9211x; 1.5094x over previous
#include <cuda_runtime.h>
#include <cstdint>
#include <cstddef>

#define BB 32
#define NN 25200
#define NCC 20
#define KK 1024
#define MAXDET 300
#define CONF_T 0.001f
#define IOU_T 0.45f

// ---------- scratch (static device allocations; no cudaMalloc) ----------
__device__ float         g_conf[BB * NN];
__device__ unsigned char g_lab [BB * NN];
__device__ float4        g_tbox[BB * KK];
__device__ float         g_tsc [BB * KK];
__device__ int           g_tlb [BB * KK];
__device__ unsigned      g_msk [BB * KK * 32];   // TRANSPOSED mask: [b][w*1024+j], bit bi => i=32w+bi suppresses j (i<j)

// ---------- kernel A: scores + argmax labels (grid-parallel DRAM stream) ----------
// Launched 3x over block sub-ranges (same total 3150 blocks) so the profiler's
// capture slot lands on k_topk.
__global__ void k_score(const float* __restrict__ pred, int blockOff) {
    __shared__ float s[256 * 25];
    int blk = blockOff + blockIdx.x;
    size_t base4 = (size_t)blk * 1600;                  // 6400 floats = 1600 float4
    const float4* p4 = (const float4*)pred + base4;
    float4* s4 = (float4*)s;
    for (int k = threadIdx.x; k < 1600; k += 256) s4[k] = p4[k];
    __syncthreads();
    const float* row = s + threadIdx.x * 25;
    float obj  = row[4];
    float best = row[5];
    int   bl   = 0;
#pragma unroll
    for (int c = 1; c < NCC; c++) {
        float v = row[5 + c];
        if (v > best) { best = v; bl = c; }             // first-max like jnp.argmax
    }
    float conf = __fmul_rn(obj, best);
    size_t r = (size_t)blk * 256 + threadIdx.x;
    g_conf[r] = conf;
    g_lab[r]  = (unsigned char)bl;
}

// ---------- kernel B1: exact stable top-1024 per batch (register-batched, single g_conf read) ----------
__global__ void __launch_bounds__(1024, 1) k_topk(const float* __restrict__ pred) {
    extern __shared__ unsigned sh[];
    unsigned long long* cand = (unsigned long long*)sh;  // 8192 keys (64 KB)
    unsigned* h    = sh + 16384;          // 2048 bucket counts (bits>>19)
    int*      ctrl = (int*)(sh + 18432);  // 16: [0]=T(bucket) [2]=cnt
    unsigned* wsc  = sh + 18448;          // 64: warp totals + tails

    int b = blockIdx.x;
    int tid = threadIdx.x;
    int lane = tid & 31, wid = tid >> 5;
    const float* sc = g_conf + (size_t)b * NN;

    h[tid] = 0; h[tid + 1024] = 0;
    if (tid < 16) ctrl[tid] = (tid == 0) ? -1 : 0;
    __syncthreads();

    // ---- batched load: all 25 conf values front-loaded (MLP ~25, one round trip) ----
    float creg[25];
#pragma unroll
    for (int c = 0; c < 25; c++) {
        int n = c * 1024 + tid;
        creg[c] = (n < NN) ? sc[n] : -1.0f;
    }
    // ---- histogram (smem atomics, spread buckets) ----
#pragma unroll
    for (int c = 0; c < 25; c++) {
        float v = creg[c];
        if (v > CONF_T) atomicAdd(&h[__float_as_uint(v) >> 19], 1u);
    }
    __syncthreads();

    // ---- threshold: suffix-scan over 1024 bucket-pairs via warp shuffles ----
    unsigned ps = h[2 * tid] + h[2 * tid + 1];
    unsigned s = ps;
#pragma unroll
    for (int off = 1; off < 32; off <<= 1) {
        unsigned v = __shfl_down_sync(0xffffffffu, s, off);
        if (lane + off < 32) s += v;
    }
    if (lane == 0) wsc[wid] = s;
    __syncthreads();
    if (wid == 0) {
        unsigned t = wsc[lane];
#pragma unroll
        for (int off = 1; off < 32; off <<= 1) {
            unsigned v = __shfl_down_sync(0xffffffffu, t, off);
            if (lane + off < 32) t += v;
        }
        unsigned tail = __shfl_down_sync(0xffffffffu, t, 1);
        if (lane == 31) tail = 0;
        wsc[32 + lane] = tail;
    }
    __syncthreads();
    unsigned S = s + wsc[32 + wid];       // suffix including pair tid
    unsigned Snext = S - ps;              // suffix of pairs > tid
    // T = max bucket whose suffix count >= KK
    if (Snext + h[2 * tid + 1] >= KK) atomicMax(&ctrl[0], 2 * tid + 1);
    else if (S >= KK)                 atomicMax(&ctrl[0], 2 * tid);
    __syncthreads();
    unsigned T = (unsigned)(ctrl[0] < 0 ? 0 : ctrl[0]);

    // ---- collect candidates straight from registers (no second g_conf pass) ----
#pragma unroll
    for (int c = 0; c < 25; c++) {
        float v = creg[c];
        if (v > CONF_T) {
            unsigned bits = __float_as_uint(v);
            if ((bits >> 19) >= T) {
                int p = atomicAdd(&ctrl[2], 1);
                if (p < 8192) {
                    unsigned n = (unsigned)(c * 1024 + tid);
                    cand[p] = ((unsigned long long)bits << 32)
                            | (unsigned long long)(0xFFFFFFFFu - n);
                }
            }
        }
    }
    __syncthreads();
    int cnt = ctrl[2]; if (cnt > 8192) cnt = 8192;

    if (cnt <= 2048) {
        // ---- hybrid bitonic sort of 2048 keys, descending ----
        for (int p = cnt + tid; p < 2048; p += 1024) cand[p] = 0ull;
        __syncthreads();
        unsigned long long va = cand[tid], vb = cand[tid + 1024];
#pragma unroll
        for (int k = 2; k <= 32; k <<= 1) {
#pragma unroll
            for (int j = k >> 1; j >= 1; j >>= 1) {
                bool lower = (tid & j) == 0;
                {
                    unsigned long long pa = __shfl_xor_sync(0xffffffffu, va, j);
                    bool dir = (tid & k) == 0;
                    va = (((dir == lower) ? (va > pa) : (va < pa))) ? va : pa;
                }
                {
                    unsigned long long pb2 = __shfl_xor_sync(0xffffffffu, vb, j);
                    bool dir = ((tid + 1024) & k) == 0;
                    vb = (((dir == lower) ? (vb > pb2) : (vb < pb2))) ? vb : pb2;
                }
            }
        }
        cand[tid] = va; cand[tid + 1024] = vb;
        __syncthreads();
        for (int k = 64; k <= 2048; k <<= 1) {
            for (int j = k >> 1; j >= 32; j >>= 1) {
                for (int t2 = tid; t2 < 2048; t2 += 1024) {
                    int ixj = t2 ^ j;
                    if (ixj > t2) {
                        unsigned long long a = cand[t2], c2 = cand[ixj];
                        if (((t2 & k) == 0) ? (a < c2) : (a > c2)) { cand[t2] = c2; cand[ixj] = a; }
                    }
                }
                __syncthreads();
            }
            va = cand[tid]; vb = cand[tid + 1024];
#pragma unroll
            for (int j = 16; j >= 1; j >>= 1) {
                bool lower = (tid & j) == 0;
                {
                    unsigned long long pa = __shfl_xor_sync(0xffffffffu, va, j);
                    bool dir = (tid & k) == 0;
                    va = (((dir == lower) ? (va > pa) : (va < pa))) ? va : pa;
                }
                {
                    unsigned long long pb2 = __shfl_xor_sync(0xffffffffu, vb, j);
                    bool dir = ((tid + 1024) & k) == 0;
                    vb = (((dir == lower) ? (vb > pb2) : (vb < pb2))) ? vb : pb2;
                }
            }
            cand[tid] = va; cand[tid + 1024] = vb;
            __syncthreads();
        }
    } else {
        // ---- generic fallback (rare): plain smem bitonic up to 8192 ----
        int n2 = 2048; while (n2 < cnt) n2 <<= 1;
        for (int p = cnt + tid; p < n2; p += 1024) cand[p] = 0ull;
        __syncthreads();
        for (int k = 2; k <= n2; k <<= 1) {
            for (int j = k >> 1; j > 0; j >>= 1) {
                for (int t2 = tid; t2 < n2; t2 += 1024) {
                    int ixj = t2 ^ j;
                    if (ixj > t2) {
                        unsigned long long a = cand[t2], c2 = cand[ixj];
                        if (((t2 & k) == 0) ? (a < c2) : (a > c2)) { cand[t2] = c2; cand[ixj] = a; }
                    }
                }
                __syncthreads();
            }
        }
    }

    // ---- emit top-1024: score, label, xywh->xyxy (non-fused to match ref) ----
    {
        unsigned long long key = cand[tid];
        unsigned sbits = (unsigned)(key >> 32);
        float score; int n;
        if (sbits) { score = __uint_as_float(sbits); n = (int)(0xFFFFFFFFu - (unsigned)key); }
        else       { score = -1.0f; n = 0; }
        const float* pr = pred + ((size_t)b * NN + n) * 25;
        float x = pr[0], y = pr[1], w = pr[2], h2 = pr[3];
        float hw = __fmul_rn(w, 0.5f), hh = __fmul_rn(h2, 0.5f);
        int idx = b * KK + tid;
        g_tbox[idx] = make_float4(__fsub_rn(x, hw), __fsub_rn(y, hh),
                                  __fadd_rn(x, hw), __fadd_rn(y, hh));
        g_tsc[idx]  = score;
        g_tlb[idx]  = (int)g_lab[(size_t)b * NN + n];
    }
}

// ---------- kernel B2: pairwise IoU -> TRANSPOSED mask, load-balanced strip pairing ----------
// Block (wp, b) handles word-strips w=wp and w=31-wp: combined j-count is constant (1056).
// g_msk[b][w*1024+j] bit bi set <=> i=32w+bi < j AND iou(i,j) > thr. top==0 words never written
// (k_nms masks the self word), all other needed words written exactly once.
__global__ void k_iou() {
    __shared__ float ix1[64], iy1[64], ix2[64], iy2[64], iar[64];
    int b = blockIdx.y, wp = blockIdx.x, tid = threadIdx.x;

    if (tid < 64) {
        int strip = (tid < 32) ? wp : (31 - wp);
        int i = strip * 32 + (tid & 31);
        float4 bx = g_tbox[b * KK + i];
        float off = __fmul_rn((float)g_tlb[b * KK + i], 4096.0f);
        // offsets applied BEFORE area: fp32 quantization at +label*4096 must match ref
        float ox1 = __fadd_rn(bx.x, off), oy1 = __fadd_rn(bx.y, off);
        float ox2 = __fadd_rn(bx.z, off), oy2 = __fadd_rn(bx.w, off);
        ix1[tid] = ox1; iy1[tid] = oy1; ix2[tid] = ox2; iy2[tid] = oy2;
        iar[tid] = __fmul_rn(__fsub_rn(ox2, ox1), __fsub_rn(oy2, oy1));
    }
    __syncthreads();

#pragma unroll
    for (int half = 0; half < 2; half++) {
        int w = half ? (31 - wp) : wp;
        int sbase = half * 32;
        for (int j = 32 * w + tid; j < 1024; j += 256) {
            float4 bx = g_tbox[b * KK + j];
            float off = __fmul_rn((float)g_tlb[b * KK + j], 4096.0f);
            float jx1 = __fadd_rn(bx.x, off), jy1 = __fadd_rn(bx.y, off);
            float jx2 = __fadd_rn(bx.z, off), jy2 = __fadd_rn(bx.w, off);
            float aj  = __fmul_rn(__fsub_rn(jx2, jx1), __fsub_rn(jy2, jy1));
            int top = j - 32 * w; if (top > 32) top = 32;
            unsigned bits = 0;
            for (int bi = 0; bi < top; bi++) {   // smem broadcast reads
                float ltx = fmaxf(jx1, ix1[sbase + bi]), lty = fmaxf(jy1, iy1[sbase + bi]);
                float rbx = fminf(jx2, ix2[sbase + bi]), rby = fminf(jy2, iy2[sbase + bi]);
                float ww = fmaxf(__fsub_rn(rbx, ltx), 0.0f);
                float hh = fmaxf(__fsub_rn(rby, lty), 0.0f);
                float inter = __fmul_rn(ww, hh);
                float den = __fadd_rn(__fsub_rn(__fadd_rn(iar[sbase + bi], aj), inter), 1e-9f);
                // margin compare: exact decision without div except in a ~1e-4 band
                float d = __fsub_rn(inter, __fmul_rn(IOU_T, den));
                float marg = __fmul_rn(den, 1e-4f);
                bool sup;
                if (fabsf(d) <= marg) sup = (inter / den) > IOU_T;   // rare exact IEEE path
                else                  sup = d > 0.0f;
                if (sup) bits |= (1u << bi);
            }
            if (top > 0) g_msk[(size_t)b * 32768 + w * 1024 + j] = bits;  // coalesced over j
        }
    }
}

// ---------- kernel B3: Jacobi-fixpoint greedy NMS + clip/filter + top-300 compaction ----------
__global__ void __launch_bounds__(1024, 1) k_nms(const int* __restrict__ imw, const int* __restrict__ imh,
                      float* __restrict__ out) {
    extern __shared__ unsigned sh[];
    unsigned* cm    = sh;                    // 32768 words, [w][j] (lower triangle valid)
    unsigned* kwsA  = sh + 32768;            // 32
    unsigned* kwsB  = sh + 32800;            // 32
    unsigned* wcnt  = sh + 32832;            // 32
    unsigned* wbal  = sh + 32864;            // 32
    int*      ctrl  = (int*)(sh + 32896);    // 4
    float4*   cbox  = (float4*)(sh + 32900); // 300 (32900*4 % 16 == 0)
    float*    cscore = (float*)(cbox + MAXDET);
    int*      clabel = (int*)(cscore + MAXDET);

    int b = blockIdx.x, tid = threadIdx.x;
    int lane = tid & 31, wid = tid >> 5;

    // vectorized lower-triangle mask load (4-aligned j groups share the same w, j>>5)
    for (int base = tid * 4; base < 32768; base += 4096) {
        int w = base >> 10, j0 = base & 1023;
        if (w <= (j0 >> 5))
            *(uint4*)(cm + base) = *(const uint4*)(g_msk + (size_t)b * 32768 + base);
    }
    float score = g_tsc[b * KK + tid];
    bool cnd = score > CONF_T;
    unsigned cbal = __ballot_sync(0xffffffffu, cnd);
    if (lane == 0) kwsA[wid] = cbal;
    __syncthreads();

    // Jacobi fixpoint: keep[j] = cand[j] & !exists(i<j: sup(i,j) & keep[i])
    // converges to the unique greedy solution; self word masked to lane-lower bits
    unsigned* cur = kwsA;
    unsigned* nxt = kwsB;
    unsigned mself = cm[wid * 1024 + tid] & ((1u << lane) - 1u);
    for (int it = 0; it < 1025; it++) {
        unsigned sup = mself & cur[wid];
        for (int w = 0; w < wid; w++)
            sup |= cm[w * 1024 + tid] & cur[w];  // lanes->consecutive j: conflict-free; cur[w] broadcast
        bool nk = cnd && (sup == 0u);
        unsigned nb = __ballot_sync(0xffffffffu, nk);
        if (lane == 0) nxt[wid] = nb;
        int changed = __syncthreads_or((int)(nb != cur[wid]));
        if (!changed) break;
        unsigned* t = cur; cur = nxt; nxt = t;
    }

    bool keep = (cur[wid] >> lane) & 1u;
    float fw = (float)(*imw), fh = (float)(*imh);
    float4 bx = g_tbox[b * KK + tid];
    float x1c = fminf(fmaxf(bx.x, 0.0f), fw);
    float y1c = fminf(fmaxf(bx.y, 0.0f), fh);
    float x2c = fminf(fmaxf(bx.z, 0.0f), fw);
    float y2c = fminf(fmaxf(bx.w, 0.0f), fh);
    float bw  = __fsub_rn(x2c, x1c);
    float bh2 = __fsub_rn(y2c, y1c);
    bool valid = keep && (bw > 0.0f) && (bh2 > 0.0f) && (bw >= 1.0f) && (bh2 >= 1.0f);

    unsigned vb = __ballot_sync(0xffffffffu, valid);
    if (lane == 0) { wcnt[wid] = __popc(vb); wbal[wid] = vb; }
    __syncthreads();
    if (tid == 0) {
        int acc2 = 0;
        for (int q = 0; q < 32; q++) { int c = wcnt[q]; wcnt[q] = acc2; acc2 += c; }
        ctrl[0] = acc2;
    }
    __syncthreads();
    if (valid) {
        int rank = wcnt[wid] + __popc(wbal[wid] & ((1u << lane) - 1u));
        if (rank < MAXDET) {
            cbox[rank]   = make_float4(x1c, y1c, x2c, y2c);
            cscore[rank] = score;
            clabel[rank] = g_tlb[b * KK + tid];
        }
    }
    __syncthreads();

    int total = ctrl[0]; if (total > MAXDET) total = MAXDET;
    if (tid < MAXDET) {
        float4 ob; float os, ol, ov;
        if (tid < total) { ob = cbox[tid]; os = cscore[tid]; ol = (float)clabel[tid]; ov = 1.0f; }
        else             { ob = make_float4(0, 0, 0, 0); os = 0.0f; ol = 0.0f; ov = 0.0f; }
        float* obox = out + ((size_t)b * MAXDET + tid) * 4;
        obox[0] = ob.x; obox[1] = ob.y; obox[2] = ob.z; obox[3] = ob.w;
        out[BB * MAXDET * 4 + b * MAXDET + tid] = os;   // det_scores
        out[BB * MAXDET * 5 + b * MAXDET + tid] = ol;   // det_labels (as f32)
        out[BB * MAXDET * 6 + b * MAXDET + tid] = ov;   // vm (as f32)
    }
}

extern "C" void kernel_launch(void* const* d_in, const int* in_sizes, int n_in,
                              void* d_out, int out_size) {
    const float* pred = (const float*)d_in[0];
    const int*   imh  = (const int*)d_in[1];
    const int*   imw  = (const int*)d_in[2];
    float* out = (float*)d_out;

    cudaFuncSetAttribute((const void*)k_topk,
                         cudaFuncAttributeMaxDynamicSharedMemorySize, 74048);
    cudaFuncSetAttribute((const void*)k_nms,
                         cudaFuncAttributeMaxDynamicSharedMemorySize, 138800);

    // k_score split into 3 sub-range launches (same 3150 blocks total);
    // shifts the ncu capture slot onto k_topk for next-round evidence.
    k_score<<<1050, 256>>>(pred, 0);
    k_score<<<1050, 256>>>(pred, 1050);
    k_score<<<1050, 256>>>(pred, 2100);
    k_topk<<<BB, 1024, 74048>>>(pred);
    k_iou<<<dim3(16, BB), 256>>>();
    k_nms<<<BB, 1024, 138800>>>(imw, imh, out);
}